// round 15
// baseline (speedup 1.0000x reference)
#include <cuda_runtime.h>

// Single kernel, fully barrier-free prep: EVERY warp computes the two real
// 3x3 bilinear forms M (observables Z0, Z1) for itself via register shuffles
// (~130 warp-instructions, no __syncthreads, no inter-warp coupling), writes
// them to its own 80-byte shared slice, then evaluates 4 samples/thread:
//   z_k = (1, X0, Y0) * M_k * (1, X1, Y1)^T,  X = cos(pi*n), Y = sin(pi*n).

__device__ __forceinline__ float bil(const float* m,
                                     float X0, float Y0, float X1, float Y1) {
    float d0 = fmaf(m[2], Y1, fmaf(m[1], X1, m[0]));
    float d1 = fmaf(m[5], Y1, fmaf(m[4], X1, m[3]));
    float d2 = fmaf(m[8], Y1, fmaf(m[7], X1, m[6]));
    return fmaf(Y0, d2, fmaf(X0, d1, d0));
}

__global__ void __launch_bounds__(256, 8) qcirc_kernel(
    const float4* __restrict__ noise, float4* __restrict__ out,
    const float* __restrict__ qw, int t)
{
    __shared__ __align__(16) float sM[8][20];   // per-warp M slices (640 B)

    const unsigned FULL = 0xFFFFFFFFu;
    int tid = threadIdx.x;
    int lane = tid & 31;
    int w = tid >> 5;

    // ===== Warp-local prep (all warps, redundant, shuffle-only) ============

    // Stage 1: sincos of the 12 half-angles in lanes 0-11 (others compute
    // lane-0's values; harmless).
    float cv, sv;
    {
        int ll = (lane < 12) ? lane : 0;
        int l = ll / 6, rem = ll % 6, ww = rem / 3, k = rem % 3;
        float phi = qw[l * 6 + ww * 3 + 0];
        float th  = qw[l * 6 + ww * 3 + 1];
        float om  = qw[l * 6 + ww * 3 + 2];
        float ang = (k == 0) ? 0.5f * th
                  : (k == 1) ? 0.5f * (phi + om)
                             : 0.5f * (phi - om);
        __sincosf(ang, &sv, &cv);
    }

    // Stage 2: gate entries in lanes 0-15 (l = lane>>3, w = (lane>>2)&1,
    // i = (lane>>1)&1, j = lane&1).  Rot = RZ(om) RY(th) RZ(phi):
    //  (0,0)=( ct*ca, -ct*sa)  (0,1)=(-st*cb, -st*sb)
    //  (1,0)=( st*cb, -st*sb)  (1,1)=( ct*ca,  ct*sa)
    float ger, gei;
    {
        int gl = (lane >> 3) & 1, gw = (lane >> 2) & 1;
        int base = gl * 6 + gw * 3;
        float ct = __shfl_sync(FULL, cv, base);
        float st = __shfl_sync(FULL, sv, base);
        float ca = __shfl_sync(FULL, cv, base + 1);
        float sa = __shfl_sync(FULL, sv, base + 1);
        float cb = __shfl_sync(FULL, cv, base + 2);
        float sb = __shfl_sync(FULL, sv, base + 2);
        int gi = (lane >> 1) & 1, gj = lane & 1;
        ger = (gi == gj) ? ct * ca : ((gi == 0) ? -st * cb : st * cb);
        gei = (gi == 0) ? ((gj == 0) ? -ct * sa : -st * sb)
                        : ((gj == 0) ? -st * sb :  ct * sa);
    }

    // Stage 3: W evolution, one complex entry per lane (q = r*4 + m,
    // r = basis row i*2+j, m = column; lanes 16-31 mirror lanes 0-15).
    float wr, wi;
    {
        int q = lane & 15;
        int qr = q >> 2, qm = q & 3;
        int qi = qr >> 1, qj = qr & 1;
        // W init = D = diag(1, -i, -i, -1)
        wr = (q == 0) ? 1.f : ((q == 15) ? -1.f : 0.f);
        wi = (q == 5 || q == 10) ? -1.f : 0.f;

        #pragma unroll
        for (int l = 0; l < 2; l++) {
            // Gate on qubit 0: new(i,j) = g0[i][0]*W(0,j) + g0[i][1]*W(1,j)
            {
                float ar = __shfl_sync(FULL, wr, qj * 4 + qm);
                float ai = __shfl_sync(FULL, wi, qj * 4 + qm);
                float br = __shfl_sync(FULL, wr, (2 + qj) * 4 + qm);
                float bi = __shfl_sync(FULL, wi, (2 + qj) * 4 + qm);
                int c0 = (l * 2 + 0) * 4 + qi * 2;
                float g0r = __shfl_sync(FULL, ger, c0);
                float g0i = __shfl_sync(FULL, gei, c0);
                float g1r = __shfl_sync(FULL, ger, c0 + 1);
                float g1i = __shfl_sync(FULL, gei, c0 + 1);
                wr = g0r * ar - g0i * ai + g1r * br - g1i * bi;
                wi = g0r * ai + g0i * ar + g1r * bi + g1i * br;
            }
            // Gate on qubit 1: new(i,j) = g1[j][0]*W(i,0) + g1[j][1]*W(i,1)
            {
                float ar = __shfl_sync(FULL, wr, (2 * qi) * 4 + qm);
                float ai = __shfl_sync(FULL, wi, (2 * qi) * 4 + qm);
                float br = __shfl_sync(FULL, wr, (2 * qi + 1) * 4 + qm);
                float bi = __shfl_sync(FULL, wi, (2 * qi + 1) * 4 + qm);
                int c0 = (l * 2 + 1) * 4 + qj * 2;
                float g0r = __shfl_sync(FULL, ger, c0);
                float g0i = __shfl_sync(FULL, gei, c0);
                float g1r = __shfl_sync(FULL, ger, c0 + 1);
                float g1i = __shfl_sync(FULL, gei, c0 + 1);
                wr = g0r * ar - g0i * ai + g1r * br - g1i * bi;
                wi = g0r * ai + g0i * ar + g1r * bi + g1i * br;
            }
            // Fused CNOT(0->1) then CNOT(1->0): new(i,j) = old(i^j, i)
            {
                int sp = ((qi ^ qj) * 2 + qi) * 4 + qm;
                float nwr = __shfl_sync(FULL, wr, sp);
                float nwi = __shfl_sync(FULL, wi, sp);
                wr = nwr; wi = nwi;
            }
        }
    }

    // Stage 4: ReA entry per lane: lane = obs*16 + jj*4 + mm,
    // ReA = Re((W^H S W))[jj][mm] for observable obs.
    float rea;
    {
        int obs = lane >> 4, jj = (lane >> 2) & 3, mm = lane & 3;
        float acc = 0.f;
        #pragma unroll
        for (int k = 0; k < 4; k++) {
            float wjr = __shfl_sync(FULL, wr, k * 4 + jj);
            float wji = __shfl_sync(FULL, wi, k * 4 + jj);
            float wmr = __shfl_sync(FULL, wr, k * 4 + mm);
            float wmi = __shfl_sync(FULL, wi, k * 4 + mm);
            float sk = (obs == 0) ? ((k < 2) ? 1.f : -1.f)
                                  : ((k & 1) ? -1.f : 1.f);
            acc += sk * (wjr * wmr + wji * wmi);
        }
        rea = acc;
    }

    // Stage 5: M entries in lanes 0-17 via 4 shuffles of rea.
    // Basis map (1,X,Y): index e has pairs  e=0:(0,0,+),(1,1,+)
    //  e=1:(0,0,+),(1,1,-)   e=2:(0,1,+),(1,0,+)
    {
        const int   A0[3] = {0, 0, 0}, B0[3] = {0, 0, 1};
        const int   A1[3] = {1, 1, 1}, B1[3] = {1, 1, 0};
        const float S1[3] = {1.f, -1.f, 1.f};
        int safe = (lane < 18) ? lane : 0;
        int obs = safe / 9, e = safe % 9, al = e / 3, be = e % 3;
        float acc = 0.f;
        #pragma unroll
        for (int p = 0; p < 2; p++) {
            int ap = p ? A1[al] : A0[al];
            int bp = p ? B1[al] : B0[al];
            float sp = p ? S1[al] : 1.f;
            #pragma unroll
            for (int qq = 0; qq < 2; qq++) {
                int aq = qq ? A1[be] : A0[be];
                int bq = qq ? B1[be] : B0[be];
                float sq = qq ? S1[be] : 1.f;
                int src = obs * 16 + (2 * ap + aq) * 4 + (2 * bp + bq);
                float v = __shfl_sync(FULL, rea, src);
                acc += sp * sq * v;
            }
        }
        if (lane < 18)      sM[w][lane] = 0.25f * acc;
        else if (lane < 20) sM[w][lane] = 0.f;
    }
    __syncwarp(FULL);

    // ===== Hot path: 4 samples/thread, two coalesced float4 streams ========
    int idx = blockIdx.x * blockDim.x + tid;
    if (idx >= t) return;

    float4 a = noise[idx];
    float4 b = noise[idx + t];

    float M[20];
    const float4* sp4 = reinterpret_cast<const float4*>(sM[w]);
    #pragma unroll
    for (int k = 0; k < 5; k++) {
        float4 v = sp4[k];
        M[4 * k + 0] = v.x; M[4 * k + 1] = v.y;
        M[4 * k + 2] = v.z; M[4 * k + 3] = v.w;
    }

    const float PI = 3.14159265358979323846f;
    float Xa, Ya, Xb, Yb, Xc, Yc, Xd, Yd;
    float4 ra, rb;

    __sincosf(a.x * PI, &Ya, &Xa);
    __sincosf(a.y * PI, &Yb, &Xb);
    __sincosf(a.z * PI, &Yc, &Xc);
    __sincosf(a.w * PI, &Yd, &Xd);
    ra.x = bil(M + 0, Xa, Ya, Xb, Yb);
    ra.y = bil(M + 9, Xa, Ya, Xb, Yb);
    ra.z = bil(M + 0, Xc, Yc, Xd, Yd);
    ra.w = bil(M + 9, Xc, Yc, Xd, Yd);

    __sincosf(b.x * PI, &Ya, &Xa);
    __sincosf(b.y * PI, &Yb, &Xb);
    __sincosf(b.z * PI, &Yc, &Xc);
    __sincosf(b.w * PI, &Yd, &Xd);
    rb.x = bil(M + 0, Xa, Ya, Xb, Yb);
    rb.y = bil(M + 9, Xa, Ya, Xb, Yb);
    rb.z = bil(M + 0, Xc, Yc, Xd, Yd);
    rb.w = bil(M + 9, Xc, Yc, Xd, Yd);

    out[idx] = ra;
    out[idx + t] = rb;
}

extern "C" void kernel_launch(void* const* d_in, const int* in_sizes, int n_in,
                              void* d_out, int out_size) {
    const float* noise = (const float*)d_in[0];     // [B, 2] f32
    const float* qw    = (const float*)d_in[1];     // [2, 2, 3] f32

    int n4 = in_sizes[0] / 4;   // float4 count
    int t = n4 / 2;             // threads; each handles float4 idx and idx+t
    int threads = 256;
    int blocks = (t + threads - 1) / threads;
    qcirc_kernel<<<blocks, threads>>>(
        (const float4*)noise, (float4*)d_out, qw, t);
}